// round 8
// baseline (speedup 1.0000x reference)
#include <cuda_runtime.h>
#include <cstdint>

#define NPTS   262144
#define NGRIDS 64
#define GS     64
#define CELLS  (GS*GS*GS)     // 262144
#define GPC    8              // grids per epoch (fp32 slab = 8 * 2.1MB, L2-resident)
#define NCHUNK (NGRIDS/GPC)   // 8
#define PBLK   (NPTS/256)     // 1024
#define NBINS  262144         // 64^3 spatial bins == grid cells

__device__ int    g_hist[NBINS];
__device__ int    g_binStart[NBINS];
__device__ int    g_bsum[1024];
__device__ float4 g_pxs[NPTS];   // sorted points: (x, y, z, bitcast(orig idx))

__device__ __forceinline__ void st256cs_f(void* p, const float* f) {
    asm volatile("st.global.cs.v8.f32 [%0], {%1,%2,%3,%4,%5,%6,%7,%8};"
        :: "l"(p), "f"(f[0]), "f"(f[1]), "f"(f[2]), "f"(f[3]),
           "f"(f[4]), "f"(f[5]), "f"(f[6]), "f"(f[7]) : "memory");
}

__device__ __forceinline__ int point_key(float tx, float ty, float tz) {
    int qx = min(max((int)((tx + 1.0f) * 32.0f), 0), 63);
    int qy = min(max((int)((ty + 1.0f) * 32.0f), 0), 63);
    int qz = min(max((int)((tz + 1.0f) * 32.0f), 0), 63);
    return (qz * GS + qy) * GS + qx;   // x fastest (matches W-contiguous grid)
}

// ---------------- sort pipeline ----------------
__global__ __launch_bounds__(256) void zero_kernel() {
    g_hist[blockIdx.x * 256 + threadIdx.x] = 0;
}
__global__ __launch_bounds__(256) void hist_kernel(const float* __restrict__ xs) {
    int n = blockIdx.x * 256 + threadIdx.x;
    atomicAdd(&g_hist[point_key(xs[n*3], xs[n*3+1], xs[n*3+2])], 1);
}
__global__ __launch_bounds__(256) void scan1_kernel() {
    __shared__ int s[256];
    int t = threadIdx.x;
    s[t] = g_hist[blockIdx.x * 256 + t];
    __syncthreads();
    for (int o = 128; o > 0; o >>= 1) {
        if (t < o) s[t] += s[t + o];
        __syncthreads();
    }
    if (t == 0) g_bsum[blockIdx.x] = s[0];
}
__global__ __launch_bounds__(1024) void scan2_kernel() {
    __shared__ int ws[32];
    int t = threadIdx.x;
    int lane = t & 31, w = t >> 5;
    int v = g_bsum[t];
    int s = v;
    #pragma unroll
    for (int o = 1; o < 32; o <<= 1) {
        int x = __shfl_up_sync(0xffffffffu, s, o);
        if (lane >= o) s += x;
    }
    if (lane == 31) ws[w] = s;
    __syncthreads();
    if (w == 0) {
        int y = ws[lane];
        #pragma unroll
        for (int o = 1; o < 32; o <<= 1) {
            int x = __shfl_up_sync(0xffffffffu, y, o);
            if (lane >= o) y += x;
        }
        ws[lane] = y;
    }
    __syncthreads();
    int off = (w > 0) ? ws[w - 1] : 0;
    g_bsum[t] = off + s - v;   // exclusive
}
__global__ __launch_bounds__(256) void scan3_kernel() {
    __shared__ int s[256];
    int t = threadIdx.x;
    int i = blockIdx.x * 256 + t;
    int v = g_hist[i];
    s[t] = v;
    __syncthreads();
    for (int o = 1; o < 256; o <<= 1) {
        int x = (t >= o) ? s[t - o] : 0;
        __syncthreads();
        s[t] += x;
        __syncthreads();
    }
    g_binStart[i] = s[t] - v + g_bsum[blockIdx.x];
}
__global__ __launch_bounds__(256) void scatter_kernel(const float* __restrict__ xs) {
    int n = blockIdx.x * 256 + threadIdx.x;
    float tx = xs[n*3], ty = xs[n*3+1], tz = xs[n*3+2];
    int pos = atomicAdd(&g_binStart[point_key(tx, ty, tz)], 1);
    g_pxs[pos] = make_float4(tx, ty, tz, __int_as_float(n));
}

// Per-dim weight fold, base b = clamp(i, 0, 62) so b and b+1 are in-bounds:
//  i in [0,62]: (1-f, f); i==-1: (f, 0); i==63: (0, 1-f); else (0,0).
__device__ __forceinline__ void dimw(float p, int& b, float& wA, float& wB) {
    float f0 = floorf(p);
    float f = p - f0;
    int i = (int)f0;
    b = min(max(i, 0), 62);
    wA = 0.0f; wB = 0.0f;
    if ((unsigned)i < 63u)      { wA = 1.0f - f; wB = f; }
    else if (i == -1)           { wA = f; }
    else if (i == 63)           { wB = 1.0f - f; }
}

// ---------------- sample (raw fp32 grid, no scratch) ----------------
__global__ __launch_bounds__(256) void sample_kernel(
    const float* __restrict__ M,      // [64, 4, 4]
    const float* __restrict__ fg,     // [64, 2, 64, 64, 64]
    float* __restrict__ out)          // [NPTS, 128]
{
    __shared__ float sM[NGRIDS * 16];
    int tid = threadIdx.x;
    for (int i = tid; i < NGRIDS * 16; i += 256) {
        float v = M[i];
        sM[i] = ((i & 3) == 3) ? 31.5f * (v + 1.0f) : 31.5f * v;
    }
    __syncthreads();

    int chunk = blockIdx.x >> 10;              // grid epoch (L2-resident slab)
    int t     = (blockIdx.x & (PBLK - 1)) * 256 + tid;

    float4 p = g_pxs[t];                       // sorted -> warp-coherent gathers
    float tx = p.x, ty = p.y, tz = p.z;
    int n = __float_as_int(p.w);

    float res[2 * GPC];

    #pragma unroll
    for (int j = 0; j < GPC; ++j) {
        int g = chunk * GPC + j;
        const float* m = sM + g * 16;
        float px = fmaf(m[0], tx, fmaf(m[1], ty, fmaf(m[2],  tz, m[3])));
        float py = fmaf(m[4], tx, fmaf(m[5], ty, fmaf(m[6],  tz, m[7])));
        float pz = fmaf(m[8], tx, fmaf(m[9], ty, fmaf(m[10], tz, m[11])));

        int xb, yb, zb;
        float wxA, wxB, wyA, wyB, wzA, wzB;
        dimw(px, xb, wxA, wxB);
        dimw(py, yb, wyA, wyB);
        dimw(pz, zb, wzA, wzB);

        const float* g0 = fg + (size_t)g * 2 * CELLS + ((zb * GS + yb) * GS + xb);
        const float* g1 = g0 + CELLS;

        // 16 scalar loads (consecutive-offset -> base reg + immediates in SASS)
        float v000a = __ldg(g0);
        float v000b = __ldg(g0 + 1);
        float v001a = __ldg(g0 + GS);
        float v001b = __ldg(g0 + GS + 1);
        float v010a = __ldg(g0 + GS*GS);
        float v010b = __ldg(g0 + GS*GS + 1);
        float v011a = __ldg(g0 + GS*GS + GS);
        float v011b = __ldg(g0 + GS*GS + GS + 1);
        float u000a = __ldg(g1);
        float u000b = __ldg(g1 + 1);
        float u001a = __ldg(g1 + GS);
        float u001b = __ldg(g1 + GS + 1);
        float u010a = __ldg(g1 + GS*GS);
        float u010b = __ldg(g1 + GS*GS + 1);
        float u011a = __ldg(g1 + GS*GS + GS);
        float u011b = __ldg(g1 + GS*GS + GS + 1);

        float w00 = wzA * wyA, w01 = wzA * wyB;
        float w10 = wzB * wyA, w11 = wzB * wyB;
        float w00A = w00 * wxA, w00B = w00 * wxB;
        float w01A = w01 * wxA, w01B = w01 * wxB;
        float w10A = w10 * wxA, w10B = w10 * wxB;
        float w11A = w11 * wxA, w11B = w11 * wxB;

        float a0, a1;
        a0 = v000a * w00A;
        a0 = fmaf(v000b, w00B, a0);
        a0 = fmaf(v001a, w01A, a0);
        a0 = fmaf(v001b, w01B, a0);
        a0 = fmaf(v010a, w10A, a0);
        a0 = fmaf(v010b, w10B, a0);
        a0 = fmaf(v011a, w11A, a0);
        a0 = fmaf(v011b, w11B, a0);
        a1 = u000a * w00A;
        a1 = fmaf(u000b, w00B, a1);
        a1 = fmaf(u001a, w01A, a1);
        a1 = fmaf(u001b, w01B, a1);
        a1 = fmaf(u010a, w10A, a1);
        a1 = fmaf(u010b, w10B, a1);
        a1 = fmaf(u011a, w11A, a1);
        a1 = fmaf(u011b, w11B, a1);

        res[2 * j]     = a0;
        res[2 * j + 1] = a1;
    }

    float* op = out + (size_t)n * (NGRIDS * 2) + chunk * (GPC * 2);
    st256cs_f(op, res);
    st256cs_f(op + 8, res + 8);
}

extern "C" void kernel_launch(void* const* d_in, const int* in_sizes, int n_in,
                              void* d_out, int out_size)
{
    const float* xs = (const float*)d_in[0];   // [262144, 3]
    const float* M  = (const float*)d_in[1];   // [64, 4, 4]
    const float* fg = (const float*)d_in[2];   // [64, 2, 64, 64, 64]
    float* out = (float*)d_out;                // [262144, 128]

    zero_kernel   <<<NBINS / 256, 256>>>();
    hist_kernel   <<<NPTS / 256, 256>>>(xs);
    scan1_kernel  <<<NBINS / 256, 256>>>();
    scan2_kernel  <<<1, 1024>>>();
    scan3_kernel  <<<NBINS / 256, 256>>>();
    scatter_kernel<<<NPTS / 256, 256>>>(xs);
    sample_kernel <<<NCHUNK * PBLK, 256>>>(M, fg, out);
}